// round 2
// baseline (speedup 1.0000x reference)
#include <cuda_runtime.h>
#include <math.h>

// Problem constants (fixed by the dataset)
#define B_DIM 16
#define N_DIM 8192
#define D_DIM 256
#define K_DIM 1024
#define R_TOTAL (B_DIM * N_DIM)   // 131072 rows

// GEMM tiling
#define BM 64
#define BN 64
#define BK 16
#define TM 4
#define TN 4
#define NTHREADS 256   // 16 x 16 thread grid

// Scratch (static device globals — no runtime allocation allowed)
__device__ float g_x2[R_TOTAL];
__device__ float g_c2[K_DIM];
__device__ float g_row_partial[R_TOTAL];

// ---------------------------------------------------------------------------
// Kernel 1: squared norms of x rows and centroid rows.
// One warp per row; each lane loads 8 floats via two float4s, warp-reduce.
// rows [0, R_TOTAL) -> x, rows [R_TOTAL, R_TOTAL+K_DIM) -> centroids
// ---------------------------------------------------------------------------
__global__ __launch_bounds__(256) void norms_kernel(const float* __restrict__ X,
                                                    const float* __restrict__ C) {
    const int warp_id = (blockIdx.x * blockDim.x + threadIdx.x) >> 5;
    const int lane = threadIdx.x & 31;
    const int total_rows = R_TOTAL + K_DIM;
    if (warp_id >= total_rows) return;

    const float* src;
    long base;
    if (warp_id < R_TOTAL) {
        src = X; base = (long)warp_id * D_DIM;
    } else {
        src = C; base = (long)(warp_id - R_TOTAL) * D_DIM;
    }
    // 256 floats / 32 lanes = 8 per lane (2 x float4)
    float acc = 0.0f;
    const float4* p = reinterpret_cast<const float4*>(src + base);
    float4 v0 = p[lane];
    float4 v1 = p[lane + 32];
    acc = v0.x * v0.x + v0.y * v0.y + v0.z * v0.z + v0.w * v0.w
        + v1.x * v1.x + v1.y * v1.y + v1.z * v1.z + v1.w * v1.w;
    #pragma unroll
    for (int off = 16; off > 0; off >>= 1)
        acc += __shfl_xor_sync(0xFFFFFFFFu, acc, off);
    if (lane == 0) {
        if (warp_id < R_TOTAL) g_x2[warp_id] = acc;
        else                   g_c2[warp_id - R_TOTAL] = acc;
    }
}

// ---------------------------------------------------------------------------
// Kernel 2: sq[row][k] = max(x2[row] + c2[k] - 2 * dot(x_row, c_k), 0)
// Classic 64x64 register-blocked SGEMM over D=256. Writes sq into `out`
// (used as scratch; kernel 3 overwrites it in-place with softmax).
// ---------------------------------------------------------------------------
__global__ __launch_bounds__(NTHREADS) void sqdist_kernel(const float* __restrict__ X,
                                                          const float* __restrict__ C,
                                                          float* __restrict__ out) {
    __shared__ float As[BK][BM];   // As[k][m] = X[rowBase+m][k0+k]
    __shared__ float Bs[BK][BN];   // Bs[k][n] = C[colBase+n][k0+k]

    const int tid = threadIdx.x;
    const int tx = tid & 15;       // 0..15 -> column group
    const int ty = tid >> 4;       // 0..15 -> row group
    const int rowBase = blockIdx.y * BM;
    const int colBase = blockIdx.x * BN;

    // load indices: each thread fetches one float4 per tile
    const int lr = tid >> 2;           // 0..63 : row within tile
    const int lc = (tid & 3) << 2;     // 0,4,8,12 : col offset within BK chunk

    float acc[TM][TN];
    #pragma unroll
    for (int i = 0; i < TM; i++)
        #pragma unroll
        for (int j = 0; j < TN; j++) acc[i][j] = 0.0f;

    for (int k0 = 0; k0 < D_DIM; k0 += BK) {
        // load A tile (64 rows x 16 dims), transpose into As[k][m]
        float4 av = *reinterpret_cast<const float4*>(
            X + (long)(rowBase + lr) * D_DIM + k0 + lc);
        As[lc + 0][lr] = av.x;
        As[lc + 1][lr] = av.y;
        As[lc + 2][lr] = av.z;
        As[lc + 3][lr] = av.w;
        // load B tile (64 centroids x 16 dims), transpose into Bs[k][n]
        float4 bv = *reinterpret_cast<const float4*>(
            C + (long)(colBase + lr) * D_DIM + k0 + lc);
        Bs[lc + 0][lr] = bv.x;
        Bs[lc + 1][lr] = bv.y;
        Bs[lc + 2][lr] = bv.z;
        Bs[lc + 3][lr] = bv.w;
        __syncthreads();

        #pragma unroll
        for (int k = 0; k < BK; k++) {
            float4 a = *reinterpret_cast<const float4*>(&As[k][ty * TM]);
            float4 b = *reinterpret_cast<const float4*>(&Bs[k][tx * TN]);
            float af[TM] = {a.x, a.y, a.z, a.w};
            float bf[TN] = {b.x, b.y, b.z, b.w};
            #pragma unroll
            for (int i = 0; i < TM; i++)
                #pragma unroll
                for (int j = 0; j < TN; j++)
                    acc[i][j] = fmaf(af[i], bf[j], acc[i][j]);
        }
        __syncthreads();
    }

    // epilogue: sq = max(x2 + c2 - 2*dot, 0)
    float c2v[TN];
    #pragma unroll
    for (int j = 0; j < TN; j++) c2v[j] = g_c2[colBase + tx * TN + j];

    #pragma unroll
    for (int i = 0; i < TM; i++) {
        const int row = rowBase + ty * TM + i;
        const float x2v = g_x2[row];
        float4 o;
        o.x = fmaxf(x2v + c2v[0] - 2.0f * acc[i][0], 0.0f);
        o.y = fmaxf(x2v + c2v[1] - 2.0f * acc[i][1], 0.0f);
        o.z = fmaxf(x2v + c2v[2] - 2.0f * acc[i][2], 0.0f);
        o.w = fmaxf(x2v + c2v[3] - 2.0f * acc[i][3], 0.0f);
        *reinterpret_cast<float4*>(out + (long)row * K_DIM + colBase + tx * TN)
            = o;
    }
}

// ---------------------------------------------------------------------------
// Kernel 3: per-row softmax over K=1024, in place.
// soft = softmax(-sqrt(sq)); also per-row loss partial sum(soft*sq).
// One block (256 threads) per row; each thread owns one float4 (4 cols).
// ---------------------------------------------------------------------------
__device__ __forceinline__ float block_reduce(float v, float* sbuf, int tid,
                                              bool is_max) {
    // warp reduce
    #pragma unroll
    for (int off = 16; off > 0; off >>= 1) {
        float o = __shfl_xor_sync(0xFFFFFFFFu, v, off);
        v = is_max ? fmaxf(v, o) : (v + o);
    }
    if ((tid & 31) == 0) sbuf[tid >> 5] = v;
    __syncthreads();
    if (tid < 32) {
        float w = (tid < 8) ? sbuf[tid] : (is_max ? -3.0e38f : 0.0f);
        #pragma unroll
        for (int off = 4; off > 0; off >>= 1) {
            float o = __shfl_xor_sync(0xFFFFFFFFu, w, off);
            w = is_max ? fmaxf(w, o) : (w + o);
        }
        if (tid == 0) sbuf[0] = w;
    }
    __syncthreads();
    float r = sbuf[0];
    __syncthreads();
    return r;
}

__global__ __launch_bounds__(256) void softmax_kernel(float* __restrict__ buf) {
    __shared__ float sbuf[8];
    const long row = blockIdx.x;
    const int tid = threadIdx.x;
    float4* rowp = reinterpret_cast<float4*>(buf + row * K_DIM);

    float4 sq = rowp[tid];
    float d0 = sqrtf(sq.x), d1 = sqrtf(sq.y), d2 = sqrtf(sq.z), d3 = sqrtf(sq.w);
    // logits = -dist (TEMPERATURE = 1)
    float lmax = fmaxf(fmaxf(-d0, -d1), fmaxf(-d2, -d3));
    lmax = block_reduce(lmax, sbuf, tid, true);

    float e0 = expf(-d0 - lmax);
    float e1 = expf(-d1 - lmax);
    float e2 = expf(-d2 - lmax);
    float e3 = expf(-d3 - lmax);
    float s = e0 + e1 + e2 + e3;
    s = block_reduce(s, sbuf, tid, false);
    float inv = 1.0f / s;

    float4 soft;
    soft.x = e0 * inv; soft.y = e1 * inv; soft.z = e2 * inv; soft.w = e3 * inv;
    rowp[tid] = soft;

    float part = soft.x * sq.x + soft.y * sq.y + soft.z * sq.z + soft.w * sq.w;
    part = block_reduce(part, sbuf, tid, false);
    if (tid == 0) g_row_partial[row] = part;
}

// ---------------------------------------------------------------------------
// Kernel 4: deterministic reduction of row partials -> loss at out[last].
// ---------------------------------------------------------------------------
__global__ __launch_bounds__(1024) void loss_kernel(float* __restrict__ out,
                                                    long loss_idx) {
    __shared__ float s[1024];
    const int tid = threadIdx.x;
    float acc = 0.0f;
    for (int i = tid; i < R_TOTAL; i += 1024) acc += g_row_partial[i];
    s[tid] = acc;
    __syncthreads();
    #pragma unroll
    for (int stride = 512; stride > 0; stride >>= 1) {
        if (tid < stride) s[tid] += s[tid + stride];
        __syncthreads();
    }
    if (tid == 0) out[loss_idx] = s[0] / (float)B_DIM;
}

// ---------------------------------------------------------------------------
extern "C" void kernel_launch(void* const* d_in, const int* in_sizes, int n_in,
                              void* d_out, int out_size) {
    const float* X = (const float*)d_in[0];   // (16, 8192, 256) fp32
    const float* C = (const float*)d_in[1];   // (1024, 256) fp32
    float* out = (float*)d_out;               // soft (B,N,K) then loss scalar
    (void)in_sizes; (void)n_in;

    // 1) norms: one warp per row, (R_TOTAL + K_DIM) rows, 8 warps/block
    {
        int total_warps = R_TOTAL + K_DIM;
        int blocks = (total_warps + 7) / 8;
        norms_kernel<<<blocks, 256>>>(X, C);
    }
    // 2) squared distances (GEMM) -> out used as scratch
    {
        dim3 grid(K_DIM / BN, R_TOTAL / BM);
        sqdist_kernel<<<grid, NTHREADS>>>(X, C, out);
    }
    // 3) softmax in place + per-row loss partials
    softmax_kernel<<<R_TOTAL, 256>>>(out);
    // 4) loss scalar
    {
        long loss_idx = (long)out_size - 1;
        loss_kernel<<<1, 1024>>>(out, loss_idx);
    }
}

// round 3
// speedup vs baseline: 1.2858x; 1.2858x over previous
#include <cuda_runtime.h>
#include <math.h>

typedef unsigned long long ull;

// Problem constants (fixed by the dataset)
#define B_DIM 16
#define N_DIM 8192
#define D_DIM 256
#define K_DIM 1024
#define R_TOTAL (B_DIM * N_DIM)   // 131072 rows

// GEMM tiling (128x128 tile, 8x8 per thread, f32x2 packed FMAs)
#define BM 128
#define BN 128
#define BK 16
#define NTHREADS 256

// Scratch (static device globals — no runtime allocation allowed)
__device__ float g_x2[R_TOTAL];
__device__ float g_c2[K_DIM];
__device__ float g_row_partial[R_TOTAL];

// ---------------------------------------------------------------------------
// f32x2 helpers (packed dual-FMA: one FMA-pipe issue = 2 fp32 FMAs)
// ---------------------------------------------------------------------------
__device__ __forceinline__ ull pack2(float lo, float hi) {
    ull r;
    asm("mov.b64 %0, {%1, %2};"
        : "=l"(r) : "r"(__float_as_uint(lo)), "r"(__float_as_uint(hi)));
    return r;
}
__device__ __forceinline__ ull dup2(float v) {
    ull r;
    asm("mov.b64 %0, {%1, %1};" : "=l"(r) : "r"(__float_as_uint(v)));
    return r;
}
__device__ __forceinline__ void unpack2(ull v, float& lo, float& hi) {
    unsigned a, b;
    asm("mov.b64 {%0, %1}, %2;" : "=r"(a), "=r"(b) : "l"(v));
    lo = __uint_as_float(a); hi = __uint_as_float(b);
}
__device__ __forceinline__ void ffma2(ull& d, ull a, ull b) {
    asm("fma.rn.f32x2 %0, %1, %2, %3;" : "=l"(d) : "l"(a), "l"(b), "l"(d));
}

// ---------------------------------------------------------------------------
// Kernel 1: squared norms of x rows and centroid rows. One warp per row.
// ---------------------------------------------------------------------------
__global__ __launch_bounds__(256) void norms_kernel(const float* __restrict__ X,
                                                    const float* __restrict__ C) {
    const int warp_id = (blockIdx.x * blockDim.x + threadIdx.x) >> 5;
    const int lane = threadIdx.x & 31;
    const int total_rows = R_TOTAL + K_DIM;
    if (warp_id >= total_rows) return;

    const float* src;
    long base;
    if (warp_id < R_TOTAL) {
        src = X; base = (long)warp_id * D_DIM;
    } else {
        src = C; base = (long)(warp_id - R_TOTAL) * D_DIM;
    }
    float acc = 0.0f;
    const float4* p = reinterpret_cast<const float4*>(src + base);
    float4 v0 = p[lane];
    float4 v1 = p[lane + 32];
    acc = v0.x * v0.x + v0.y * v0.y + v0.z * v0.z + v0.w * v0.w
        + v1.x * v1.x + v1.y * v1.y + v1.z * v1.z + v1.w * v1.w;
    #pragma unroll
    for (int off = 16; off > 0; off >>= 1)
        acc += __shfl_xor_sync(0xFFFFFFFFu, acc, off);
    if (lane == 0) {
        if (warp_id < R_TOTAL) g_x2[warp_id] = acc;
        else                   g_c2[warp_id - R_TOTAL] = acc;
    }
}

// ---------------------------------------------------------------------------
// Kernel 2: sq[row][k] = max(x2[row] + c2[k] - 2 * dot(x_row, c_k), 0)
// 128x128 tile SGEMM, 8x8 per thread, accumulators held as f32x2 pairs.
// ---------------------------------------------------------------------------
__global__ __launch_bounds__(NTHREADS) void sqdist_kernel(const float* __restrict__ X,
                                                          const float* __restrict__ C,
                                                          float* __restrict__ out) {
    __shared__ float As[BK][BM];   // As[k][m] = X[rowBase+m][k0+k]
    __shared__ float Bs[BK][BN];   // Bs[k][n] = C[colBase+n][k0+k]

    const int tid = threadIdx.x;
    const int tx = tid & 15;       // col group: cols tx*8 .. tx*8+7
    const int ty = tid >> 4;       // row group: rows ty*8 .. ty*8+7
    const int rowBase = blockIdx.y * BM;
    const int colBase = blockIdx.x * BN;

    // load indices: each thread fetches two float4 per operand tile
    const int lr = tid >> 2;           // 0..63 : row within half-tile
    const int lc = (tid & 3) << 2;     // 0,4,8,12 : dim offset in BK chunk

    ull acc[8][4];                 // acc[i][j] holds cols {2j, 2j+1} of row i
    #pragma unroll
    for (int i = 0; i < 8; i++)
        #pragma unroll
        for (int j = 0; j < 4; j++) acc[i][j] = 0ULL;

    for (int k0 = 0; k0 < D_DIM; k0 += BK) {
        float4 av0 = *reinterpret_cast<const float4*>(
            X + (long)(rowBase + lr) * D_DIM + k0 + lc);
        float4 av1 = *reinterpret_cast<const float4*>(
            X + (long)(rowBase + lr + 64) * D_DIM + k0 + lc);
        float4 bv0 = *reinterpret_cast<const float4*>(
            C + (long)(colBase + lr) * D_DIM + k0 + lc);
        float4 bv1 = *reinterpret_cast<const float4*>(
            C + (long)(colBase + lr + 64) * D_DIM + k0 + lc);

        __syncthreads();   // protect previous iteration's reads
        As[lc + 0][lr] = av0.x;  As[lc + 1][lr] = av0.y;
        As[lc + 2][lr] = av0.z;  As[lc + 3][lr] = av0.w;
        As[lc + 0][lr + 64] = av1.x;  As[lc + 1][lr + 64] = av1.y;
        As[lc + 2][lr + 64] = av1.z;  As[lc + 3][lr + 64] = av1.w;
        Bs[lc + 0][lr] = bv0.x;  Bs[lc + 1][lr] = bv0.y;
        Bs[lc + 2][lr] = bv0.z;  Bs[lc + 3][lr] = bv0.w;
        Bs[lc + 0][lr + 64] = bv1.x;  Bs[lc + 1][lr + 64] = bv1.y;
        Bs[lc + 2][lr + 64] = bv1.z;  Bs[lc + 3][lr + 64] = bv1.w;
        __syncthreads();

        #pragma unroll
        for (int k = 0; k < BK; k++) {
            float4 a0 = *reinterpret_cast<const float4*>(&As[k][ty * 8]);
            float4 a1 = *reinterpret_cast<const float4*>(&As[k][ty * 8 + 4]);
            float4 b0 = *reinterpret_cast<const float4*>(&Bs[k][tx * 8]);
            float4 b1 = *reinterpret_cast<const float4*>(&Bs[k][tx * 8 + 4]);

            ull bp[4];
            bp[0] = pack2(b0.x, b0.y);  bp[1] = pack2(b0.z, b0.w);
            bp[2] = pack2(b1.x, b1.y);  bp[3] = pack2(b1.z, b1.w);

            float af[8] = {a0.x, a0.y, a0.z, a0.w, a1.x, a1.y, a1.z, a1.w};
            #pragma unroll
            for (int i = 0; i < 8; i++) {
                ull ad = dup2(af[i]);
                #pragma unroll
                for (int j = 0; j < 4; j++)
                    ffma2(acc[i][j], ad, bp[j]);
            }
        }
    }

    // epilogue: sq = max(x2 + c2 - 2*dot, 0)
    float c2v[8];
    #pragma unroll
    for (int j = 0; j < 8; j++) c2v[j] = g_c2[colBase + tx * 8 + j];

    #pragma unroll
    for (int i = 0; i < 8; i++) {
        const int row = rowBase + ty * 8 + i;
        const float x2v = g_x2[row];
        float d[8];
        #pragma unroll
        for (int j = 0; j < 4; j++) unpack2(acc[i][j], d[2 * j], d[2 * j + 1]);
        float4 o0, o1;
        o0.x = fmaxf(x2v + c2v[0] - 2.0f * d[0], 0.0f);
        o0.y = fmaxf(x2v + c2v[1] - 2.0f * d[1], 0.0f);
        o0.z = fmaxf(x2v + c2v[2] - 2.0f * d[2], 0.0f);
        o0.w = fmaxf(x2v + c2v[3] - 2.0f * d[3], 0.0f);
        o1.x = fmaxf(x2v + c2v[4] - 2.0f * d[4], 0.0f);
        o1.y = fmaxf(x2v + c2v[5] - 2.0f * d[5], 0.0f);
        o1.z = fmaxf(x2v + c2v[6] - 2.0f * d[6], 0.0f);
        o1.w = fmaxf(x2v + c2v[7] - 2.0f * d[7], 0.0f);
        float* dst = out + (long)row * K_DIM + colBase + tx * 8;
        *reinterpret_cast<float4*>(dst)     = o0;
        *reinterpret_cast<float4*>(dst + 4) = o1;
    }
}

// ---------------------------------------------------------------------------
// Kernel 3: per-row softmax over K=1024, in place + per-row loss partial.
// ---------------------------------------------------------------------------
__device__ __forceinline__ float block_reduce(float v, float* sbuf, int tid,
                                              bool is_max) {
    #pragma unroll
    for (int off = 16; off > 0; off >>= 1) {
        float o = __shfl_xor_sync(0xFFFFFFFFu, v, off);
        v = is_max ? fmaxf(v, o) : (v + o);
    }
    if ((tid & 31) == 0) sbuf[tid >> 5] = v;
    __syncthreads();
    if (tid < 32) {
        float w = (tid < 8) ? sbuf[tid] : (is_max ? -3.0e38f : 0.0f);
        #pragma unroll
        for (int off = 4; off > 0; off >>= 1) {
            float o = __shfl_xor_sync(0xFFFFFFFFu, w, off);
            w = is_max ? fmaxf(w, o) : (w + o);
        }
        if (tid == 0) sbuf[0] = w;
    }
    __syncthreads();
    float r = sbuf[0];
    __syncthreads();
    return r;
}

__global__ __launch_bounds__(256) void softmax_kernel(float* __restrict__ buf) {
    __shared__ float sbuf[8];
    const long row = blockIdx.x;
    const int tid = threadIdx.x;
    float4* rowp = reinterpret_cast<float4*>(buf + row * K_DIM);

    float4 sq = rowp[tid];
    float d0 = sqrtf(sq.x), d1 = sqrtf(sq.y), d2 = sqrtf(sq.z), d3 = sqrtf(sq.w);
    float lmax = fmaxf(fmaxf(-d0, -d1), fmaxf(-d2, -d3));
    lmax = block_reduce(lmax, sbuf, tid, true);

    float e0 = expf(-d0 - lmax);
    float e1 = expf(-d1 - lmax);
    float e2 = expf(-d2 - lmax);
    float e3 = expf(-d3 - lmax);
    float s = e0 + e1 + e2 + e3;
    s = block_reduce(s, sbuf, tid, false);
    float inv = 1.0f / s;

    float4 soft;
    soft.x = e0 * inv; soft.y = e1 * inv; soft.z = e2 * inv; soft.w = e3 * inv;
    rowp[tid] = soft;

    float part = soft.x * sq.x + soft.y * sq.y + soft.z * sq.z + soft.w * sq.w;
    part = block_reduce(part, sbuf, tid, false);
    if (tid == 0) g_row_partial[row] = part;
}

// ---------------------------------------------------------------------------
// Kernel 4: deterministic reduction of row partials -> loss at out[last].
// ---------------------------------------------------------------------------
__global__ __launch_bounds__(1024) void loss_kernel(float* __restrict__ out,
                                                    long loss_idx) {
    __shared__ float s[1024];
    const int tid = threadIdx.x;
    float acc = 0.0f;
    for (int i = tid; i < R_TOTAL; i += 1024) acc += g_row_partial[i];
    s[tid] = acc;
    __syncthreads();
    #pragma unroll
    for (int stride = 512; stride > 0; stride >>= 1) {
        if (tid < stride) s[tid] += s[tid + stride];
        __syncthreads();
    }
    if (tid == 0) out[loss_idx] = s[0] / (float)B_DIM;
}

// ---------------------------------------------------------------------------
extern "C" void kernel_launch(void* const* d_in, const int* in_sizes, int n_in,
                              void* d_out, int out_size) {
    const float* X = (const float*)d_in[0];   // (16, 8192, 256) fp32
    const float* C = (const float*)d_in[1];   // (1024, 256) fp32
    float* out = (float*)d_out;               // soft (B,N,K) then loss scalar
    (void)in_sizes; (void)n_in;

    // 1) norms
    {
        int total_warps = R_TOTAL + K_DIM;
        int blocks = (total_warps + 7) / 8;
        norms_kernel<<<blocks, 256>>>(X, C);
    }
    // 2) squared distances (f32x2 packed SGEMM) -> out used as scratch
    {
        dim3 grid(K_DIM / BN, R_TOTAL / BM);   // (8, 1024)
        sqdist_kernel<<<grid, NTHREADS>>>(X, C, out);
    }
    // 3) softmax in place + per-row loss partials
    softmax_kernel<<<R_TOTAL, 256>>>(out);
    // 4) loss scalar
    {
        long loss_idx = (long)out_size - 1;
        loss_kernel<<<1, 1024>>>(out, loss_idx);
    }
}

// round 6
// speedup vs baseline: 2.4365x; 1.8950x over previous
#include <cuda_runtime.h>
#include <cuda_bf16.h>
#include <math.h>
#include <stdint.h>

typedef unsigned long long ull;

// Problem constants (fixed by the dataset)
#define B_DIM 16
#define N_DIM 8192
#define D_DIM 256
#define K_DIM 1024
#define R_TOTAL (B_DIM * N_DIM)     // 131072 rows
#define KSPLIT 512                  // packed [hi(256) | lo(256)] bf16

// GEMM tiling: 128x128 CTA tile, 8 warps of 64x32, K chunks of 64 bf16
#define BMT 128
#define BNT 128
#define CHUNK_K 64                  // 128 bytes per row per stage
#define NCHUNK 12                   // 3-term split: (hi,hi)x4, (lo,hi)x4, (hi,lo)x4
#define NSTAGE 3
#define A_STAGE 16384               // 128 rows * 128 B
#define B_STAGE 16384
#define STAGE_BYTES (A_STAGE + B_STAGE)
#define SMEM_DYN (NSTAGE * STAGE_BYTES)   // 98304

// Scratch (static device globals — no runtime allocation allowed)
__device__ __nv_bfloat16 g_xsplit[(size_t)R_TOTAL * KSPLIT];
__device__ __nv_bfloat16 g_csplit[(size_t)K_DIM * KSPLIT];
__device__ float g_x2[R_TOTAL];
__device__ float g_c2[K_DIM];
__device__ float g_row_partial[R_TOTAL];

// ---------------------------------------------------------------------------
// Helpers (baseline sm_80+ features only — harness compiles at target sm_103)
// ---------------------------------------------------------------------------
__device__ __forceinline__ uint32_t smem_u32(const void* p) {
    uint32_t a;
    asm("{ .reg .u64 t; cvta.to.shared.u64 t, %1; cvt.u32.u64 %0, t; }"
        : "=r"(a) : "l"(p));
    return a;
}
#define SWZ128(o) ((o) ^ (((o) >> 3) & 0x70))

__device__ __forceinline__ void cp_async16(uint32_t dst, const void* src) {
    asm volatile("cp.async.cg.shared.global [%0], [%1], 16;"
                 :: "r"(dst), "l"(src));
}
#define CP_COMMIT()  asm volatile("cp.async.commit_group;")
#define CP_WAIT_2()  asm volatile("cp.async.wait_group 2;")
#define CP_WAIT_0()  asm volatile("cp.async.wait_group 0;")

__device__ __forceinline__ void ldsm_x4(uint32_t& r0, uint32_t& r1,
                                        uint32_t& r2, uint32_t& r3,
                                        uint32_t addr) {
    asm volatile("ldmatrix.sync.aligned.m8n8.x4.shared.b16 {%0,%1,%2,%3}, [%4];"
                 : "=r"(r0), "=r"(r1), "=r"(r2), "=r"(r3) : "r"(addr));
}

__device__ __forceinline__ void mma_16816(float* c, const uint32_t* a,
                                          const uint32_t* b) {
    asm volatile(
        "mma.sync.aligned.m16n8k16.row.col.f32.bf16.bf16.f32 "
        "{%0,%1,%2,%3}, {%4,%5,%6,%7}, {%8,%9}, {%0,%1,%2,%3};"
        : "+f"(c[0]), "+f"(c[1]), "+f"(c[2]), "+f"(c[3])
        : "r"(a[0]), "r"(a[1]), "r"(a[2]), "r"(a[3]), "r"(b[0]), "r"(b[1]));
}

// ---------------------------------------------------------------------------
// Kernel 1: bf16 hi/lo split prepack + squared norms. One warp per row.
// ---------------------------------------------------------------------------
__global__ __launch_bounds__(256) void prepack_kernel(const float* __restrict__ X,
                                                      const float* __restrict__ C) {
    const int warp_id = (blockIdx.x * blockDim.x + threadIdx.x) >> 5;
    const int lane = threadIdx.x & 31;
    if (warp_id >= R_TOTAL + K_DIM) return;

    const float* src;
    __nv_bfloat16* dst;
    float* nrm;
    long r;
    if (warp_id < R_TOTAL) { src = X; dst = g_xsplit; nrm = g_x2; r = warp_id; }
    else { src = C; dst = g_csplit; nrm = g_c2; r = warp_id - R_TOTAL; }

    const float4* p = reinterpret_cast<const float4*>(src + r * D_DIM);
    float4 va = p[lane * 2];
    float4 vb = p[lane * 2 + 1];
    float v[8] = {va.x, va.y, va.z, va.w, vb.x, vb.y, vb.z, vb.w};

    union { __nv_bfloat16 h[8]; uint4 u; } hi, lo;
    float acc = 0.0f;
    #pragma unroll
    for (int i = 0; i < 8; i++) {
        acc = fmaf(v[i], v[i], acc);
        __nv_bfloat16 h = __float2bfloat16(v[i]);
        hi.h[i] = h;
        lo.h[i] = __float2bfloat16(v[i] - __bfloat162float(h));
    }
    #pragma unroll
    for (int off = 16; off > 0; off >>= 1)
        acc += __shfl_xor_sync(0xFFFFFFFFu, acc, off);
    if (lane == 0) nrm[r] = acc;

    *reinterpret_cast<uint4*>(dst + r * KSPLIT + lane * 8) = hi.u;
    *reinterpret_cast<uint4*>(dst + r * KSPLIT + 256 + lane * 8) = lo.u;
}

// ---------------------------------------------------------------------------
// Kernel 2: sq = max(x2 + c2 - 2*dot, 0) via HMMA (mma.sync bf16, f32 accum).
// 3-term split: dot = hi_x.hi_c + lo_x.hi_c + hi_x.lo_c  (chunk offset remap).
// 128x128 tile/CTA, 8 warps x (64x32), cp.async 3-stage pipeline.
// ---------------------------------------------------------------------------
__device__ __forceinline__ void load_stage(uint32_t a_s, uint32_t b_s,
                                           int rowBase, int colBase,
                                           int aoff, int boff, int tid) {
    #pragma unroll
    for (int it = 0; it < 4; it++) {
        int idx = it * 256 + tid;        // 0..1023 : 128 rows x 8 chunks
        int row = idx >> 3, j = idx & 7;
        cp_async16(a_s + SWZ128(row * 128 + j * 16),
                   g_xsplit + (size_t)(rowBase + row) * KSPLIT + aoff + j * 8);
        cp_async16(b_s + SWZ128(row * 128 + j * 16),
                   g_csplit + (size_t)(colBase + row) * KSPLIT + boff + j * 8);
    }
}

__global__ __launch_bounds__(256, 2) void sqdist_hmma_kernel(float* __restrict__ out) {
    extern __shared__ char smem[];
    const uint32_t sbase = smem_u32(smem);
    const int tid = threadIdx.x;
    const int wid = tid >> 5;
    const int lane = tid & 31;
    const int rowBase = blockIdx.y * BMT;
    const int colBase = blockIdx.x * BNT;
    const int warp_m = (wid >> 2) * 64;   // 0 or 64
    const int warp_n = (wid & 3) * 32;    // 0,32,64,96

    uint32_t a_s[NSTAGE], b_s[NSTAGE];
    #pragma unroll
    for (int s = 0; s < NSTAGE; s++) {
        a_s[s] = sbase + s * STAGE_BYTES;
        b_s[s] = a_s[s] + A_STAGE;
    }

    // chunk -> offsets into the 512-wide packed arrays
    // chunks 0-3: (hi,hi); 4-7: (lo,hi); 8-11: (hi,lo)
    const int aofs[NCHUNK] = {0, 64, 128, 192, 256, 320, 384, 448, 0, 64, 128, 192};
    const int bofs[NCHUNK] = {0, 64, 128, 192, 0, 64, 128, 192, 256, 320, 384, 448};

    float acc[4][4][4];
    #pragma unroll
    for (int mt = 0; mt < 4; mt++)
        #pragma unroll
        for (int nt = 0; nt < 4; nt++)
            #pragma unroll
            for (int q = 0; q < 4; q++) acc[mt][nt][q] = 0.0f;

    // prologue: fill 3 stages
    #pragma unroll
    for (int c = 0; c < NSTAGE; c++) {
        load_stage(a_s[c], b_s[c], rowBase, colBase, aofs[c], bofs[c], tid);
        CP_COMMIT();
    }

    const uint32_t lrow = lane & 15;
    const uint32_t lkb = (lane >> 4) << 4;     // 0 or 16 bytes

    for (int c = 0; c < NCHUNK; c++) {
        CP_WAIT_2();
        __syncthreads();
        const int s = c % NSTAGE;
        const uint32_t a_cur = a_s[s], b_cur = b_s[s];

        #pragma unroll
        for (int ks = 0; ks < 4; ks++) {
            const uint32_t kb = ks * 32 + lkb;
            uint32_t af[4][4];
            #pragma unroll
            for (int mt = 0; mt < 4; mt++) {
                uint32_t row = warp_m + mt * 16 + lrow;
                ldsm_x4(af[mt][0], af[mt][1], af[mt][2], af[mt][3],
                        a_cur + SWZ128(row * 128 + kb));
            }
            uint32_t bf[4][2];
            #pragma unroll
            for (int nt2 = 0; nt2 < 2; nt2++) {
                uint32_t row = warp_n + nt2 * 16 + lrow;
                uint32_t m0, m1, m2, m3;
                ldsm_x4(m0, m1, m2, m3, b_cur + SWZ128(row * 128 + kb));
                bf[nt2 * 2 + 0][0] = m0; bf[nt2 * 2 + 0][1] = m2;
                bf[nt2 * 2 + 1][0] = m1; bf[nt2 * 2 + 1][1] = m3;
            }
            #pragma unroll
            for (int mt = 0; mt < 4; mt++)
                #pragma unroll
                for (int nt = 0; nt < 4; nt++)
                    mma_16816(acc[mt][nt], af[mt], bf[nt]);
        }

        __syncthreads();
        if (c + NSTAGE < NCHUNK)
            load_stage(a_s[s], b_s[s], rowBase, colBase,
                       aofs[c + NSTAGE], bofs[c + NSTAGE], tid);
        CP_COMMIT();
    }
    CP_WAIT_0();

    // epilogue: sq = max(x2 + c2 - 2*dot, 0)
    const int tgrp = lane >> 2;           // 0..7 (row within 8)
    const int tpair = (lane & 3) * 2;     // 0,2,4,6 (col pair)
    #pragma unroll
    for (int mt = 0; mt < 4; mt++) {
        const int m0 = rowBase + warp_m + mt * 16 + tgrp;
        const float x2a = __ldg(&g_x2[m0]);
        const float x2b = __ldg(&g_x2[m0 + 8]);
        #pragma unroll
        for (int nt = 0; nt < 4; nt++) {
            const int n = colBase + warp_n + nt * 8 + tpair;
            const float c2a = __ldg(&g_c2[n]);
            const float c2b = __ldg(&g_c2[n + 1]);
            float2 v0, v1;
            v0.x = fmaxf(x2a + c2a - 2.0f * acc[mt][nt][0], 0.0f);
            v0.y = fmaxf(x2a + c2b - 2.0f * acc[mt][nt][1], 0.0f);
            v1.x = fmaxf(x2b + c2a - 2.0f * acc[mt][nt][2], 0.0f);
            v1.y = fmaxf(x2b + c2b - 2.0f * acc[mt][nt][3], 0.0f);
            *reinterpret_cast<float2*>(out + (size_t)m0 * K_DIM + n) = v0;
            *reinterpret_cast<float2*>(out + (size_t)(m0 + 8) * K_DIM + n) = v1;
        }
    }
}

// ---------------------------------------------------------------------------
// Kernel 3: per-row softmax over K=1024, in place + per-row loss partial.
// ---------------------------------------------------------------------------
__device__ __forceinline__ float block_reduce(float v, float* sbuf, int tid,
                                              bool is_max) {
    #pragma unroll
    for (int off = 16; off > 0; off >>= 1) {
        float o = __shfl_xor_sync(0xFFFFFFFFu, v, off);
        v = is_max ? fmaxf(v, o) : (v + o);
    }
    if ((tid & 31) == 0) sbuf[tid >> 5] = v;
    __syncthreads();
    if (tid < 32) {
        float w = (tid < 8) ? sbuf[tid] : (is_max ? -3.0e38f : 0.0f);
        #pragma unroll
        for (int off = 4; off > 0; off >>= 1) {
            float o = __shfl_xor_sync(0xFFFFFFFFu, w, off);
            w = is_max ? fmaxf(w, o) : (w + o);
        }
        if (tid == 0) sbuf[0] = w;
    }
    __syncthreads();
    float r = sbuf[0];
    __syncthreads();
    return r;
}

__global__ __launch_bounds__(256) void softmax_kernel(float* __restrict__ buf) {
    __shared__ float sbuf[8];
    const long row = blockIdx.x;
    const int tid = threadIdx.x;
    float4* rowp = reinterpret_cast<float4*>(buf + row * K_DIM);

    float4 sq = rowp[tid];
    float d0 = sqrtf(sq.x), d1 = sqrtf(sq.y), d2 = sqrtf(sq.z), d3 = sqrtf(sq.w);
    float lmax = fmaxf(fmaxf(-d0, -d1), fmaxf(-d2, -d3));
    lmax = block_reduce(lmax, sbuf, tid, true);

    float e0 = expf(-d0 - lmax);
    float e1 = expf(-d1 - lmax);
    float e2 = expf(-d2 - lmax);
    float e3 = expf(-d3 - lmax);
    float s = e0 + e1 + e2 + e3;
    s = block_reduce(s, sbuf, tid, false);
    float inv = 1.0f / s;

    float4 soft;
    soft.x = e0 * inv; soft.y = e1 * inv; soft.z = e2 * inv; soft.w = e3 * inv;
    rowp[tid] = soft;

    float part = soft.x * sq.x + soft.y * sq.y + soft.z * sq.z + soft.w * sq.w;
    part = block_reduce(part, sbuf, tid, false);
    if (tid == 0) g_row_partial[row] = part;
}

// ---------------------------------------------------------------------------
// Kernel 4: deterministic reduction of row partials -> loss at out[last].
// ---------------------------------------------------------------------------
__global__ __launch_bounds__(1024) void loss_kernel(float* __restrict__ out,
                                                    long loss_idx) {
    __shared__ float s[1024];
    const int tid = threadIdx.x;
    float acc = 0.0f;
    for (int i = tid; i < R_TOTAL; i += 1024) acc += g_row_partial[i];
    s[tid] = acc;
    __syncthreads();
    #pragma unroll
    for (int stride = 512; stride > 0; stride >>= 1) {
        if (tid < stride) s[tid] += s[tid + stride];
        __syncthreads();
    }
    if (tid == 0) out[loss_idx] = s[0] / (float)B_DIM;
}

// ---------------------------------------------------------------------------
extern "C" void kernel_launch(void* const* d_in, const int* in_sizes, int n_in,
                              void* d_out, int out_size) {
    const float* X = (const float*)d_in[0];   // (16, 8192, 256) fp32
    const float* C = (const float*)d_in[1];   // (1024, 256) fp32
    float* out = (float*)d_out;               // soft (B,N,K) then loss scalar
    (void)in_sizes; (void)n_in;

    // 1) bf16 split + norms
    {
        int total_warps = R_TOTAL + K_DIM;
        int blocks = (total_warps + 7) / 8;
        prepack_kernel<<<blocks, 256>>>(X, C);
    }
    // 2) squared distances via HMMA GEMM -> out used as scratch
    {
        cudaFuncSetAttribute(sqdist_hmma_kernel,
                             cudaFuncAttributeMaxDynamicSharedMemorySize,
                             SMEM_DYN);
        dim3 grid(K_DIM / BNT, R_TOTAL / BMT);   // (8, 1024)
        sqdist_hmma_kernel<<<grid, 256, SMEM_DYN>>>(out);
    }
    // 3) softmax in place + per-row loss partials
    softmax_kernel<<<R_TOTAL, 256>>>(out);
    // 4) loss scalar
    {
        long loss_idx = (long)out_size - 1;
        loss_kernel<<<1, 1024>>>(out, loss_idx);
    }
}

// round 8
// speedup vs baseline: 3.0426x; 1.2487x over previous
#include <cuda_runtime.h>
#include <cuda_fp16.h>
#include <math.h>
#include <stdint.h>

typedef unsigned long long ull;

// Problem constants (fixed by the dataset)
#define B_DIM 16
#define N_DIM 8192
#define D_DIM 256
#define K_DIM 1024
#define R_TOTAL (B_DIM * N_DIM)     // 131072 rows
#define KSPLIT 512                  // packed [hi(256) | lo(256)] fp16

// GEMM tiling: 128x128 CTA tile, 8 warps of 64x32, K chunks of 64 fp16
#define BMT 128
#define BNT 128
#define CHUNK_K 64                  // 128 bytes per row per stage
#define NCHUNK 8                    // fp16 2-term split: (hi,hi)x4, (lo,hi)x4
#define NSTAGE 3
#define A_STAGE 16384               // 128 rows * 128 B
#define B_STAGE 16384
#define STAGE_BYTES (A_STAGE + B_STAGE)
#define SMEM_DYN (NSTAGE * STAGE_BYTES)   // 98304

// Scratch (static device globals — no runtime allocation allowed)
__device__ __half g_xsplit[(size_t)R_TOTAL * KSPLIT];
__device__ __half g_csplit[(size_t)K_DIM * KSPLIT];
__device__ float g_x2[R_TOTAL];
__device__ float g_c2[K_DIM];
__device__ float g_row_partial[R_TOTAL];

// ---------------------------------------------------------------------------
// Helpers (baseline sm_80+ features only — harness compiles at target sm_103)
// ---------------------------------------------------------------------------
__device__ __forceinline__ uint32_t smem_u32(const void* p) {
    uint32_t a;
    asm("{ .reg .u64 t; cvta.to.shared.u64 t, %1; cvt.u32.u64 %0, t; }"
        : "=r"(a) : "l"(p));
    return a;
}
#define SWZ128(o) ((o) ^ (((o) >> 3) & 0x70))

__device__ __forceinline__ void cp_async16(uint32_t dst, const void* src) {
    asm volatile("cp.async.cg.shared.global [%0], [%1], 16;"
                 :: "r"(dst), "l"(src));
}
#define CP_COMMIT()  asm volatile("cp.async.commit_group;")
#define CP_WAIT_2()  asm volatile("cp.async.wait_group 2;")
#define CP_WAIT_0()  asm volatile("cp.async.wait_group 0;")

__device__ __forceinline__ void ldsm_x4(uint32_t& r0, uint32_t& r1,
                                        uint32_t& r2, uint32_t& r3,
                                        uint32_t addr) {
    asm volatile("ldmatrix.sync.aligned.m8n8.x4.shared.b16 {%0,%1,%2,%3}, [%4];"
                 : "=r"(r0), "=r"(r1), "=r"(r2), "=r"(r3) : "r"(addr));
}

__device__ __forceinline__ void mma_16816(float* c, const uint32_t* a,
                                          const uint32_t* b) {
    asm volatile(
        "mma.sync.aligned.m16n8k16.row.col.f32.f16.f16.f32 "
        "{%0,%1,%2,%3}, {%4,%5,%6,%7}, {%8,%9}, {%0,%1,%2,%3};"
        : "+f"(c[0]), "+f"(c[1]), "+f"(c[2]), "+f"(c[3])
        : "r"(a[0]), "r"(a[1]), "r"(a[2]), "r"(a[3]), "r"(b[0]), "r"(b[1]));
}

// ---------------------------------------------------------------------------
// Kernel 1: fp16 hi/lo split prepack + squared norms. One warp per row.
// hi = fp16(x); lo = fp16(x - hi). dot ≈ hi_x.hi_c + lo_x.hi_c (22-bit eff.)
// ---------------------------------------------------------------------------
__global__ __launch_bounds__(256) void prepack_kernel(const float* __restrict__ X,
                                                      const float* __restrict__ C) {
    const int warp_id = (blockIdx.x * blockDim.x + threadIdx.x) >> 5;
    const int lane = threadIdx.x & 31;
    if (warp_id >= R_TOTAL + K_DIM) return;

    const float* src;
    __half* dst;
    float* nrm;
    long r;
    if (warp_id < R_TOTAL) { src = X; dst = g_xsplit; nrm = g_x2; r = warp_id; }
    else { src = C; dst = g_csplit; nrm = g_c2; r = warp_id - R_TOTAL; }

    const float4* p = reinterpret_cast<const float4*>(src + r * D_DIM);
    float4 va = p[lane * 2];
    float4 vb = p[lane * 2 + 1];
    float v[8] = {va.x, va.y, va.z, va.w, vb.x, vb.y, vb.z, vb.w};

    union { __half h[8]; uint4 u; } hi, lo;
    float acc = 0.0f;
    #pragma unroll
    for (int i = 0; i < 8; i++) {
        acc = fmaf(v[i], v[i], acc);
        __half h = __float2half_rn(v[i]);
        hi.h[i] = h;
        lo.h[i] = __float2half_rn(v[i] - __half2float(h));
    }
    #pragma unroll
    for (int off = 16; off > 0; off >>= 1)
        acc += __shfl_xor_sync(0xFFFFFFFFu, acc, off);
    if (lane == 0) nrm[r] = acc;

    *reinterpret_cast<uint4*>(dst + r * KSPLIT + lane * 8) = hi.u;
    *reinterpret_cast<uint4*>(dst + r * KSPLIT + 256 + lane * 8) = lo.u;
}

// ---------------------------------------------------------------------------
// Kernel 2: sq = max(x2 + c2 - 2*dot, 0) via HMMA (mma.sync fp16, f32 accum).
// 2-term split: dot = hi_x.hi_c + lo_x.hi_c  (chunk offset remap).
// 128x128 tile/CTA, 8 warps x (64x32), cp.async 3-stage pipeline.
// ---------------------------------------------------------------------------
__device__ __forceinline__ void load_stage(uint32_t a_s, uint32_t b_s,
                                           int rowBase, int colBase,
                                           int aoff, int boff, int tid) {
    #pragma unroll
    for (int it = 0; it < 4; it++) {
        int idx = it * 256 + tid;        // 0..1023 : 128 rows x 8 chunks
        int row = idx >> 3, j = idx & 7;
        cp_async16(a_s + SWZ128(row * 128 + j * 16),
                   g_xsplit + (size_t)(rowBase + row) * KSPLIT + aoff + j * 8);
        cp_async16(b_s + SWZ128(row * 128 + j * 16),
                   g_csplit + (size_t)(colBase + row) * KSPLIT + boff + j * 8);
    }
}

__global__ __launch_bounds__(256, 2) void sqdist_hmma_kernel(float* __restrict__ out) {
    extern __shared__ char smem[];
    const uint32_t sbase = smem_u32(smem);
    const int tid = threadIdx.x;
    const int wid = tid >> 5;
    const int lane = tid & 31;
    const int rowBase = blockIdx.y * BMT;
    const int colBase = blockIdx.x * BNT;
    const int warp_m = (wid >> 2) * 64;   // 0 or 64
    const int warp_n = (wid & 3) * 32;    // 0,32,64,96

    uint32_t a_s[NSTAGE], b_s[NSTAGE];
    #pragma unroll
    for (int s = 0; s < NSTAGE; s++) {
        a_s[s] = sbase + s * STAGE_BYTES;
        b_s[s] = a_s[s] + A_STAGE;
    }

    // chunk -> offsets into the 512-wide packed arrays
    // chunks 0-3: (hi,hi); 4-7: (lo,hi)
    const int aofs[NCHUNK] = {0, 64, 128, 192, 256, 320, 384, 448};
    const int bofs[NCHUNK] = {0, 64, 128, 192, 0, 64, 128, 192};

    float acc[4][4][4];
    #pragma unroll
    for (int mt = 0; mt < 4; mt++)
        #pragma unroll
        for (int nt = 0; nt < 4; nt++)
            #pragma unroll
            for (int q = 0; q < 4; q++) acc[mt][nt][q] = 0.0f;

    // prologue: fill 3 stages
    #pragma unroll
    for (int c = 0; c < NSTAGE; c++) {
        load_stage(a_s[c], b_s[c], rowBase, colBase, aofs[c], bofs[c], tid);
        CP_COMMIT();
    }

    const uint32_t lrow = lane & 15;
    const uint32_t lkb = (lane >> 4) << 4;     // 0 or 16 bytes

    for (int c = 0; c < NCHUNK; c++) {
        CP_WAIT_2();
        __syncthreads();
        const int s = c % NSTAGE;
        const uint32_t a_cur = a_s[s], b_cur = b_s[s];

        #pragma unroll
        for (int ks = 0; ks < 4; ks++) {
            const uint32_t kb = ks * 32 + lkb;
            uint32_t af[4][4];
            #pragma unroll
            for (int mt = 0; mt < 4; mt++) {
                uint32_t row = warp_m + mt * 16 + lrow;
                ldsm_x4(af[mt][0], af[mt][1], af[mt][2], af[mt][3],
                        a_cur + SWZ128(row * 128 + kb));
            }
            uint32_t bf[4][2];
            #pragma unroll
            for (int nt2 = 0; nt2 < 2; nt2++) {
                uint32_t row = warp_n + nt2 * 16 + lrow;
                uint32_t m0, m1, m2, m3;
                ldsm_x4(m0, m1, m2, m3, b_cur + SWZ128(row * 128 + kb));
                bf[nt2 * 2 + 0][0] = m0; bf[nt2 * 2 + 0][1] = m2;
                bf[nt2 * 2 + 1][0] = m1; bf[nt2 * 2 + 1][1] = m3;
            }
            #pragma unroll
            for (int mt = 0; mt < 4; mt++)
                #pragma unroll
                for (int nt = 0; nt < 4; nt++)
                    mma_16816(acc[mt][nt], af[mt], bf[nt]);
        }

        __syncthreads();
        if (c + NSTAGE < NCHUNK)
            load_stage(a_s[s], b_s[s], rowBase, colBase,
                       aofs[c + NSTAGE], bofs[c + NSTAGE], tid);
        CP_COMMIT();
    }
    CP_WAIT_0();

    // epilogue: sq = max(x2 + c2 - 2*dot, 0)
    const int tgrp = lane >> 2;           // 0..7 (row within 8)
    const int tpair = (lane & 3) * 2;     // 0,2,4,6 (col pair)
    #pragma unroll
    for (int mt = 0; mt < 4; mt++) {
        const int m0 = rowBase + warp_m + mt * 16 + tgrp;
        const float x2a = __ldg(&g_x2[m0]);
        const float x2b = __ldg(&g_x2[m0 + 8]);
        #pragma unroll
        for (int nt = 0; nt < 4; nt++) {
            const int n = colBase + warp_n + nt * 8 + tpair;
            const float c2a = __ldg(&g_c2[n]);
            const float c2b = __ldg(&g_c2[n + 1]);
            float2 v0, v1;
            v0.x = fmaxf(x2a + c2a - 2.0f * acc[mt][nt][0], 0.0f);
            v0.y = fmaxf(x2a + c2b - 2.0f * acc[mt][nt][1], 0.0f);
            v1.x = fmaxf(x2b + c2a - 2.0f * acc[mt][nt][2], 0.0f);
            v1.y = fmaxf(x2b + c2b - 2.0f * acc[mt][nt][3], 0.0f);
            *reinterpret_cast<float2*>(out + (size_t)m0 * K_DIM + n) = v0;
            *reinterpret_cast<float2*>(out + (size_t)(m0 + 8) * K_DIM + n) = v1;
        }
    }
}

// ---------------------------------------------------------------------------
// Kernel 3: per-row softmax over K=1024, in place + per-row loss partial.
// ---------------------------------------------------------------------------
__device__ __forceinline__ float block_reduce(float v, float* sbuf, int tid,
                                              bool is_max) {
    #pragma unroll
    for (int off = 16; off > 0; off >>= 1) {
        float o = __shfl_xor_sync(0xFFFFFFFFu, v, off);
        v = is_max ? fmaxf(v, o) : (v + o);
    }
    if ((tid & 31) == 0) sbuf[tid >> 5] = v;
    __syncthreads();
    if (tid < 32) {
        float w = (tid < 8) ? sbuf[tid] : (is_max ? -3.0e38f : 0.0f);
        #pragma unroll
        for (int off = 4; off > 0; off >>= 1) {
            float o = __shfl_xor_sync(0xFFFFFFFFu, w, off);
            w = is_max ? fmaxf(w, o) : (w + o);
        }
        if (tid == 0) sbuf[0] = w;
    }
    __syncthreads();
    float r = sbuf[0];
    __syncthreads();
    return r;
}

__global__ __launch_bounds__(256) void softmax_kernel(float* __restrict__ buf) {
    __shared__ float sbuf[8];
    const long row = blockIdx.x;
    const int tid = threadIdx.x;
    float4* rowp = reinterpret_cast<float4*>(buf + row * K_DIM);

    float4 sq = rowp[tid];
    float d0 = sqrtf(sq.x), d1 = sqrtf(sq.y), d2 = sqrtf(sq.z), d3 = sqrtf(sq.w);
    float lmax = fmaxf(fmaxf(-d0, -d1), fmaxf(-d2, -d3));
    lmax = block_reduce(lmax, sbuf, tid, true);

    float e0 = expf(-d0 - lmax);
    float e1 = expf(-d1 - lmax);
    float e2 = expf(-d2 - lmax);
    float e3 = expf(-d3 - lmax);
    float s = e0 + e1 + e2 + e3;
    s = block_reduce(s, sbuf, tid, false);
    float inv = 1.0f / s;

    float4 soft;
    soft.x = e0 * inv; soft.y = e1 * inv; soft.z = e2 * inv; soft.w = e3 * inv;
    rowp[tid] = soft;

    float part = soft.x * sq.x + soft.y * sq.y + soft.z * sq.z + soft.w * sq.w;
    part = block_reduce(part, sbuf, tid, false);
    if (tid == 0) g_row_partial[row] = part;
}

// ---------------------------------------------------------------------------
// Kernel 4: deterministic reduction of row partials -> loss at out[last].
// ---------------------------------------------------------------------------
__global__ __launch_bounds__(1024) void loss_kernel(float* __restrict__ out,
                                                    long loss_idx) {
    __shared__ float s[1024];
    const int tid = threadIdx.x;
    float acc = 0.0f;
    for (int i = tid; i < R_TOTAL; i += 1024) acc += g_row_partial[i];
    s[tid] = acc;
    __syncthreads();
    #pragma unroll
    for (int stride = 512; stride > 0; stride >>= 1) {
        if (tid < stride) s[tid] += s[tid + stride];
        __syncthreads();
    }
    if (tid == 0) out[loss_idx] = s[0] / (float)B_DIM;
}

// ---------------------------------------------------------------------------
extern "C" void kernel_launch(void* const* d_in, const int* in_sizes, int n_in,
                              void* d_out, int out_size) {
    const float* X = (const float*)d_in[0];   // (16, 8192, 256) fp32
    const float* C = (const float*)d_in[1];   // (1024, 256) fp32
    float* out = (float*)d_out;               // soft (B,N,K) then loss scalar
    (void)in_sizes; (void)n_in;

    // 1) fp16 split + norms
    {
        int total_warps = R_TOTAL + K_DIM;
        int blocks = (total_warps + 7) / 8;
        prepack_kernel<<<blocks, 256>>>(X, C);
    }
    // 2) squared distances via HMMA GEMM -> out used as scratch
    {
        cudaFuncSetAttribute(sqdist_hmma_kernel,
                             cudaFuncAttributeMaxDynamicSharedMemorySize,
                             SMEM_DYN);
        dim3 grid(K_DIM / BNT, R_TOTAL / BMT);   // (8, 1024)
        sqdist_hmma_kernel<<<grid, 256, SMEM_DYN>>>(out);
    }
    // 3) softmax in place + per-row loss partials
    softmax_kernel<<<R_TOTAL, 256>>>(out);
    // 4) loss scalar
    {
        long loss_idx = (long)out_size - 1;
        loss_kernel<<<1, 1024>>>(out, loss_idx);
    }
}

// round 9
// speedup vs baseline: 3.1385x; 1.0316x over previous
#include <cuda_runtime.h>
#include <cuda_fp16.h>
#include <math.h>
#include <stdint.h>

typedef unsigned long long ull;

// Problem constants (fixed by the dataset)
#define B_DIM 16
#define N_DIM 8192
#define D_DIM 256
#define K_DIM 1024
#define R_TOTAL (B_DIM * N_DIM)     // 131072 rows
#define KSPLIT 512                  // packed [hi(256) | lo(256)] fp16

// GEMM tiling: 128x256 CTA tile, 8 warps of 64x64, K chunks of 64 fp16
#define BMT 128
#define BNT 256
#define CHUNK_K 64                  // 128 bytes per row per stage
#define NCHUNK 8                    // fp16 2-term split: (hi,hi)x4, (lo,hi)x4
#define NSTAGE 3
#define A_STAGE 16384               // 128 rows * 128 B
#define B_STAGE 32768               // 256 rows * 128 B
#define STAGE_BYTES (A_STAGE + B_STAGE)
#define SMEM_DYN (NSTAGE * STAGE_BYTES)   // 147456

// Scratch (static device globals — no runtime allocation allowed)
__device__ __half g_xsplit[(size_t)R_TOTAL * KSPLIT];
__device__ __half g_csplit[(size_t)K_DIM * KSPLIT];
__device__ float g_x2[R_TOTAL];
__device__ float g_c2[K_DIM];
__device__ float g_row_partial[R_TOTAL];

// ---------------------------------------------------------------------------
// Helpers (baseline sm_80+ features only — harness compiles at target sm_103)
// ---------------------------------------------------------------------------
__device__ __forceinline__ uint32_t smem_u32(const void* p) {
    uint32_t a;
    asm("{ .reg .u64 t; cvta.to.shared.u64 t, %1; cvt.u32.u64 %0, t; }"
        : "=r"(a) : "l"(p));
    return a;
}
#define SWZ128(o) ((o) ^ (((o) >> 3) & 0x70))

__device__ __forceinline__ void cp_async16(uint32_t dst, const void* src) {
    asm volatile("cp.async.cg.shared.global [%0], [%1], 16;"
                 :: "r"(dst), "l"(src));
}
#define CP_COMMIT()  asm volatile("cp.async.commit_group;")
#define CP_WAIT_1()  asm volatile("cp.async.wait_group 1;")
#define CP_WAIT_0()  asm volatile("cp.async.wait_group 0;")

__device__ __forceinline__ void ldsm_x4(uint32_t& r0, uint32_t& r1,
                                        uint32_t& r2, uint32_t& r3,
                                        uint32_t addr) {
    asm volatile("ldmatrix.sync.aligned.m8n8.x4.shared.b16 {%0,%1,%2,%3}, [%4];"
                 : "=r"(r0), "=r"(r1), "=r"(r2), "=r"(r3) : "r"(addr));
}

__device__ __forceinline__ void mma_16816(float* c, const uint32_t* a,
                                          const uint32_t* b) {
    asm volatile(
        "mma.sync.aligned.m16n8k16.row.col.f32.f16.f16.f32 "
        "{%0,%1,%2,%3}, {%4,%5,%6,%7}, {%8,%9}, {%0,%1,%2,%3};"
        : "+f"(c[0]), "+f"(c[1]), "+f"(c[2]), "+f"(c[3])
        : "r"(a[0]), "r"(a[1]), "r"(a[2]), "r"(a[3]), "r"(b[0]), "r"(b[1]));
}

// ---------------------------------------------------------------------------
// Kernel 1: fp16 hi/lo split prepack + squared norms. One warp per row.
// ---------------------------------------------------------------------------
__global__ __launch_bounds__(256) void prepack_kernel(const float* __restrict__ X,
                                                      const float* __restrict__ C) {
    const int warp_id = (blockIdx.x * blockDim.x + threadIdx.x) >> 5;
    const int lane = threadIdx.x & 31;
    if (warp_id >= R_TOTAL + K_DIM) return;

    const float* src;
    __half* dst;
    float* nrm;
    long r;
    if (warp_id < R_TOTAL) { src = X; dst = g_xsplit; nrm = g_x2; r = warp_id; }
    else { src = C; dst = g_csplit; nrm = g_c2; r = warp_id - R_TOTAL; }

    const float4* p = reinterpret_cast<const float4*>(src + r * D_DIM);
    float4 va = p[lane * 2];
    float4 vb = p[lane * 2 + 1];
    float v[8] = {va.x, va.y, va.z, va.w, vb.x, vb.y, vb.z, vb.w};

    union { __half h[8]; uint4 u; } hi, lo;
    float acc = 0.0f;
    #pragma unroll
    for (int i = 0; i < 8; i++) {
        acc = fmaf(v[i], v[i], acc);
        __half h = __float2half_rn(v[i]);
        hi.h[i] = h;
        lo.h[i] = __float2half_rn(v[i] - __half2float(h));
    }
    #pragma unroll
    for (int off = 16; off > 0; off >>= 1)
        acc += __shfl_xor_sync(0xFFFFFFFFu, acc, off);
    if (lane == 0) nrm[r] = acc;

    *reinterpret_cast<uint4*>(dst + r * KSPLIT + lane * 8) = hi.u;
    *reinterpret_cast<uint4*>(dst + r * KSPLIT + 256 + lane * 8) = lo.u;
}

// ---------------------------------------------------------------------------
// Kernel 2: sq = max(x2 + c2 - 2*dot, 0) via HMMA (mma.sync fp16, f32 accum).
// 2-term split: dot = hi_x.hi_c + lo_x.hi_c.
// 128x256 tile/CTA, 8 warps x (64x64), cp.async single-sync pipeline.
// ---------------------------------------------------------------------------
__device__ __forceinline__ void load_stage(uint32_t a_s, uint32_t b_s,
                                           int rowBase, int colBase,
                                           int aoff, int boff, int tid) {
    #pragma unroll
    for (int it = 0; it < 4; it++) {         // A: 128 rows x 8 chunks
        int idx = it * 256 + tid;
        int row = idx >> 3, j = idx & 7;
        cp_async16(a_s + SWZ128(row * 128 + j * 16),
                   g_xsplit + (size_t)(rowBase + row) * KSPLIT + aoff + j * 8);
    }
    #pragma unroll
    for (int it = 0; it < 8; it++) {         // B: 256 rows x 8 chunks
        int idx = it * 256 + tid;
        int row = idx >> 3, j = idx & 7;
        cp_async16(b_s + SWZ128(row * 128 + j * 16),
                   g_csplit + (size_t)(colBase + row) * KSPLIT + boff + j * 8);
    }
}

__global__ __launch_bounds__(256, 1) void sqdist_hmma_kernel(float* __restrict__ out) {
    extern __shared__ char smem[];
    const uint32_t sbase = smem_u32(smem);
    const int tid = threadIdx.x;
    const int wid = tid >> 5;
    const int lane = tid & 31;
    const int rowBase = blockIdx.y * BMT;
    const int colBase = blockIdx.x * BNT;
    const int warp_m = (wid >> 2) * 64;   // 0 or 64
    const int warp_n = (wid & 3) * 64;    // 0,64,128,192

    uint32_t a_s[NSTAGE], b_s[NSTAGE];
    #pragma unroll
    for (int s = 0; s < NSTAGE; s++) {
        a_s[s] = sbase + s * STAGE_BYTES;
        b_s[s] = a_s[s] + A_STAGE;
    }

    // chunk -> offsets into the 512-wide packed arrays
    const int aofs[NCHUNK] = {0, 64, 128, 192, 256, 320, 384, 448};
    const int bofs[NCHUNK] = {0, 64, 128, 192, 0, 64, 128, 192};

    float acc[4][8][4];
    #pragma unroll
    for (int mt = 0; mt < 4; mt++)
        #pragma unroll
        for (int nt = 0; nt < 8; nt++)
            #pragma unroll
            for (int q = 0; q < 4; q++) acc[mt][nt][q] = 0.0f;

    // prologue: fill NSTAGE-1 stages
    #pragma unroll
    for (int c = 0; c < NSTAGE - 1; c++) {
        load_stage(a_s[c], b_s[c], rowBase, colBase, aofs[c], bofs[c], tid);
        CP_COMMIT();
    }

    const uint32_t lrow = lane & 15;
    const uint32_t lkb = (lane >> 4) << 4;     // 0 or 16 bytes

    for (int c = 0; c < NCHUNK; c++) {
        CP_WAIT_1();
        __syncthreads();   // stage c ready; all warps done computing stage c-1
        const int s = c % NSTAGE;

        // prefetch chunk c+NSTAGE-1 into the buffer freed by chunk c-1
        if (c + NSTAGE - 1 < NCHUNK) {
            const int pf = c + NSTAGE - 1;
            const int ps = pf % NSTAGE;
            load_stage(a_s[ps], b_s[ps], rowBase, colBase,
                       aofs[pf], bofs[pf], tid);
        }
        CP_COMMIT();

        const uint32_t a_cur = a_s[s], b_cur = b_s[s];
        #pragma unroll
        for (int ks = 0; ks < 4; ks++) {
            const uint32_t kb = ks * 32 + lkb;
            uint32_t af[4][4];
            #pragma unroll
            for (int mt = 0; mt < 4; mt++) {
                uint32_t row = warp_m + mt * 16 + lrow;
                ldsm_x4(af[mt][0], af[mt][1], af[mt][2], af[mt][3],
                        a_cur + SWZ128(row * 128 + kb));
            }
            uint32_t bf[8][2];
            #pragma unroll
            for (int nt2 = 0; nt2 < 4; nt2++) {
                uint32_t row = warp_n + nt2 * 16 + lrow;
                uint32_t m0, m1, m2, m3;
                ldsm_x4(m0, m1, m2, m3, b_cur + SWZ128(row * 128 + kb));
                bf[nt2 * 2 + 0][0] = m0; bf[nt2 * 2 + 0][1] = m2;
                bf[nt2 * 2 + 1][0] = m1; bf[nt2 * 2 + 1][1] = m3;
            }
            #pragma unroll
            for (int mt = 0; mt < 4; mt++)
                #pragma unroll
                for (int nt = 0; nt < 8; nt++)
                    mma_16816(acc[mt][nt], af[mt], bf[nt]);
        }
    }
    CP_WAIT_0();

    // epilogue: sq = max(x2 + c2 - 2*dot, 0)
    const int tgrp = lane >> 2;           // 0..7 (row within 8)
    const int tpair = (lane & 3) * 2;     // 0,2,4,6 (col pair)
    #pragma unroll
    for (int mt = 0; mt < 4; mt++) {
        const int m0 = rowBase + warp_m + mt * 16 + tgrp;
        const float x2a = __ldg(&g_x2[m0]);
        const float x2b = __ldg(&g_x2[m0 + 8]);
        #pragma unroll
        for (int nt = 0; nt < 8; nt++) {
            const int n = colBase + warp_n + nt * 8 + tpair;
            const float c2a = __ldg(&g_c2[n]);
            const float c2b = __ldg(&g_c2[n + 1]);
            float2 v0, v1;
            v0.x = fmaxf(x2a + c2a - 2.0f * acc[mt][nt][0], 0.0f);
            v0.y = fmaxf(x2a + c2b - 2.0f * acc[mt][nt][1], 0.0f);
            v1.x = fmaxf(x2b + c2a - 2.0f * acc[mt][nt][2], 0.0f);
            v1.y = fmaxf(x2b + c2b - 2.0f * acc[mt][nt][3], 0.0f);
            *reinterpret_cast<float2*>(out + (size_t)m0 * K_DIM + n) = v0;
            *reinterpret_cast<float2*>(out + (size_t)(m0 + 8) * K_DIM + n) = v1;
        }
    }
}

// ---------------------------------------------------------------------------
// Kernel 3: per-row softmax over K=1024, in place + per-row loss partial.
// No max-subtraction: logits = -dist with dist in [0, ~45], exp(-d) is safely
// inside fp32 range, and softmax is shift-invariant. One fused (sum, e.sq)
// float2 reduction.
// ---------------------------------------------------------------------------
__global__ __launch_bounds__(256) void softmax_kernel(float* __restrict__ buf) {
    __shared__ float2 sbuf[8];
    const long row = blockIdx.x;
    const int tid = threadIdx.x;
    float4* rowp = reinterpret_cast<float4*>(buf + row * K_DIM);

    float4 sq = rowp[tid];
    float e0 = expf(-sqrtf(sq.x));
    float e1 = expf(-sqrtf(sq.y));
    float e2 = expf(-sqrtf(sq.z));
    float e3 = expf(-sqrtf(sq.w));

    float2 v;
    v.x = e0 + e1 + e2 + e3;                                     // sum e
    v.y = e0 * sq.x + e1 * sq.y + e2 * sq.z + e3 * sq.w;         // sum e*sq

    #pragma unroll
    for (int off = 16; off > 0; off >>= 1) {
        v.x += __shfl_xor_sync(0xFFFFFFFFu, v.x, off);
        v.y += __shfl_xor_sync(0xFFFFFFFFu, v.y, off);
    }
    if ((tid & 31) == 0) sbuf[tid >> 5] = v;
    __syncthreads();
    if (tid < 32) {
        float2 w = (tid < 8) ? sbuf[tid] : make_float2(0.0f, 0.0f);
        #pragma unroll
        for (int off = 4; off > 0; off >>= 1) {
            w.x += __shfl_xor_sync(0xFFFFFFFFu, w.x, off);
            w.y += __shfl_xor_sync(0xFFFFFFFFu, w.y, off);
        }
        if (tid == 0) sbuf[0] = w;
    }
    __syncthreads();
    const float s = sbuf[0].x;
    const float part = sbuf[0].y;
    const float inv = 1.0f / s;

    float4 soft;
    soft.x = e0 * inv; soft.y = e1 * inv; soft.z = e2 * inv; soft.w = e3 * inv;
    rowp[tid] = soft;

    if (tid == 0) g_row_partial[row] = part * inv;
}

// ---------------------------------------------------------------------------
// Kernel 4: deterministic reduction of row partials -> loss at out[last].
// ---------------------------------------------------------------------------
__global__ __launch_bounds__(1024) void loss_kernel(float* __restrict__ out,
                                                    long loss_idx) {
    __shared__ float s[1024];
    const int tid = threadIdx.x;
    float acc = 0.0f;
    for (int i = tid; i < R_TOTAL; i += 1024) acc += g_row_partial[i];
    s[tid] = acc;
    __syncthreads();
    #pragma unroll
    for (int stride = 512; stride > 0; stride >>= 1) {
        if (tid < stride) s[tid] += s[tid + stride];
        __syncthreads();
    }
    if (tid == 0) out[loss_idx] = s[0] / (float)B_DIM;
}

// ---------------------------------------------------------------------------
extern "C" void kernel_launch(void* const* d_in, const int* in_sizes, int n_in,
                              void* d_out, int out_size) {
    const float* X = (const float*)d_in[0];   // (16, 8192, 256) fp32
    const float* C = (const float*)d_in[1];   // (1024, 256) fp32
    float* out = (float*)d_out;               // soft (B,N,K) then loss scalar
    (void)in_sizes; (void)n_in;

    // 1) fp16 split + norms
    {
        int total_warps = R_TOTAL + K_DIM;
        int blocks = (total_warps + 7) / 8;
        prepack_kernel<<<blocks, 256>>>(X, C);
    }
    // 2) squared distances via HMMA GEMM -> out used as scratch
    {
        cudaFuncSetAttribute(sqdist_hmma_kernel,
                             cudaFuncAttributeMaxDynamicSharedMemorySize,
                             SMEM_DYN);
        dim3 grid(K_DIM / BNT, R_TOTAL / BMT);   // (4, 1024)
        sqdist_hmma_kernel<<<grid, 256, SMEM_DYN>>>(out);
    }
    // 3) softmax in place + per-row loss partials
    softmax_kernel<<<R_TOTAL, 256>>>(out);
    // 4) loss scalar
    {
        long loss_idx = (long)out_size - 1;
        loss_kernel<<<1, 1024>>>(out, loss_idx);
    }
}

// round 14
// speedup vs baseline: 4.5736x; 1.4572x over previous
#include <cuda_runtime.h>
#include <cuda_fp16.h>
#include <math.h>
#include <stdint.h>

typedef unsigned long long ull;

// Problem constants (fixed by the dataset)
#define B_DIM 16
#define N_DIM 8192
#define D_DIM 256
#define K_DIM 1024
#define R_TOTAL (B_DIM * N_DIM)     // 131072 rows

// GEMM tiling: 128x128 CTA tile, 8 warps of 64x32, K chunks of 64 fp16
#define BMT 128
#define BNT 128
#define NCHUNK 4                    // single-term fp16: K=256 = 4 chunks of 64
#define NSTAGE 3
#define A_STAGE 16384               // 128 rows * 128 B
#define B_STAGE 16384
#define STAGE_BYTES (A_STAGE + B_STAGE)
#define SMEM_DYN (NSTAGE * STAGE_BYTES)   // 98304 bytes -> 2 CTAs/SM

// Scratch (static device globals — no runtime allocation allowed)
__device__ __half g_xh[(size_t)R_TOTAL * D_DIM];
__device__ __half g_ch[(size_t)K_DIM * D_DIM];
__device__ float g_x2[R_TOTAL];
__device__ float g_c2[K_DIM];
__device__ float g_row_partial[R_TOTAL];

// ---------------------------------------------------------------------------
// Helpers: strictly sm_80-era features (harness builds at ptx target sm_103,
// which rejects tcgen05/TMEM; mma.sync + cp.async are the supported path).
// ---------------------------------------------------------------------------
__device__ __forceinline__ uint32_t smem_u32(const void* p) {
    uint32_t a;
    asm("{ .reg .u64 t; cvta.to.shared.u64 t, %1; cvt.u32.u64 %0, t; }"
        : "=r"(a) : "l"(p));
    return a;
}
#define SWZ128(o) ((o) ^ (((o) >> 3) & 0x70))

__device__ __forceinline__ void cp_async16(uint32_t dst, const void* src) {
    asm volatile("cp.async.cg.shared.global [%0], [%1], 16;"
                 :: "r"(dst), "l"(src));
}
#define CP_COMMIT()  asm volatile("cp.async.commit_group;")
#define CP_WAIT_1()  asm volatile("cp.async.wait_group 1;")
#define CP_WAIT_0()  asm volatile("cp.async.wait_group 0;")

__device__ __forceinline__ void ldsm_x4(uint32_t& r0, uint32_t& r1,
                                        uint32_t& r2, uint32_t& r3,
                                        uint32_t addr) {
    asm volatile("ldmatrix.sync.aligned.m8n8.x4.shared.b16 {%0,%1,%2,%3}, [%4];"
                 : "=r"(r0), "=r"(r1), "=r"(r2), "=r"(r3) : "r"(addr));
}

__device__ __forceinline__ void mma_16816(float* c, const uint32_t* a,
                                          const uint32_t* b) {
    asm volatile(
        "mma.sync.aligned.m16n8k16.row.col.f32.f16.f16.f32 "
        "{%0,%1,%2,%3}, {%4,%5,%6,%7}, {%8,%9}, {%0,%1,%2,%3};"
        : "+f"(c[0]), "+f"(c[1]), "+f"(c[2]), "+f"(c[3])
        : "r"(a[0]), "r"(a[1]), "r"(a[2]), "r"(a[3]), "r"(b[0]), "r"(b[1]));
}

// ---------------------------------------------------------------------------
// Kernel 1: fp16 convert + fp32 squared norms. One warp per row.
// Norms are computed in exact fp32; only the GEMM dot uses fp16 operands.
// ---------------------------------------------------------------------------
__global__ __launch_bounds__(256) void prepack_kernel(const float* __restrict__ X,
                                                      const float* __restrict__ C) {
    const int warp_id = (blockIdx.x * blockDim.x + threadIdx.x) >> 5;
    const int lane = threadIdx.x & 31;
    if (warp_id >= R_TOTAL + K_DIM) return;

    const float* src;
    __half* dst;
    float* nrm;
    long r;
    if (warp_id < R_TOTAL) { src = X; dst = g_xh; nrm = g_x2; r = warp_id; }
    else { src = C; dst = g_ch; nrm = g_c2; r = warp_id - R_TOTAL; }

    const float4* p = reinterpret_cast<const float4*>(src + r * D_DIM);
    float4 va = p[lane * 2];
    float4 vb = p[lane * 2 + 1];
    float v[8] = {va.x, va.y, va.z, va.w, vb.x, vb.y, vb.z, vb.w};

    union { __half h[8]; uint4 u; } hv;
    float acc = 0.0f;
    #pragma unroll
    for (int i = 0; i < 8; i++) {
        acc = fmaf(v[i], v[i], acc);
        hv.h[i] = __float2half_rn(v[i]);
    }
    #pragma unroll
    for (int off = 16; off > 0; off >>= 1)
        acc += __shfl_xor_sync(0xFFFFFFFFu, acc, off);
    if (lane == 0) nrm[r] = acc;

    *reinterpret_cast<uint4*>(dst + r * D_DIM + lane * 8) = hv.u;
}

// ---------------------------------------------------------------------------
// Kernel 2: sq = max(x2 + c2 - 2*dot, 0) via HMMA fp16, K=256.
// 128x128 tile/CTA, 8 warps x (64x32), cp.async single-sync 3-stage pipeline,
// 2 CTAs/SM.
// ---------------------------------------------------------------------------
__device__ __forceinline__ void load_stage(uint32_t a_s, uint32_t b_s,
                                           int rowBase, int colBase,
                                           int koff, int tid) {
    #pragma unroll
    for (int it = 0; it < 4; it++) {         // A tile: 128 rows x 8 x 16B
        int idx = it * 256 + tid;
        int row = idx >> 3, j = idx & 7;
        cp_async16(a_s + SWZ128(row * 128 + j * 16),
                   g_xh + (size_t)(rowBase + row) * D_DIM + koff + j * 8);
    }
    #pragma unroll
    for (int it = 0; it < 4; it++) {         // B tile: 128 rows x 8 x 16B
        int idx = it * 256 + tid;
        int row = idx >> 3, j = idx & 7;
        cp_async16(b_s + SWZ128(row * 128 + j * 16),
                   g_ch + (size_t)(colBase + row) * D_DIM + koff + j * 8);
    }
}

__global__ __launch_bounds__(256, 2) void sqdist_hmma_kernel(float* __restrict__ out) {
    extern __shared__ char smem[];
    const uint32_t sbase = smem_u32(smem);
    const int tid = threadIdx.x;
    const int wid = tid >> 5;
    const int lane = tid & 31;
    const int rowBase = blockIdx.y * BMT;
    const int colBase = blockIdx.x * BNT;
    const int warp_m = (wid >> 2) * 64;   // 0 or 64
    const int warp_n = (wid & 3) * 32;    // 0,32,64,96

    uint32_t a_s[NSTAGE], b_s[NSTAGE];
    #pragma unroll
    for (int s = 0; s < NSTAGE; s++) {
        a_s[s] = sbase + s * STAGE_BYTES;
        b_s[s] = a_s[s] + A_STAGE;
    }

    float acc[4][4][4];
    #pragma unroll
    for (int mt = 0; mt < 4; mt++)
        #pragma unroll
        for (int nt = 0; nt < 4; nt++)
            #pragma unroll
            for (int q = 0; q < 4; q++) acc[mt][nt][q] = 0.0f;

    // prologue: fill NSTAGE-1 stages with chunks 0..NSTAGE-2
    #pragma unroll
    for (int c = 0; c < NSTAGE - 1; c++) {
        load_stage(a_s[c], b_s[c], rowBase, colBase, c * 64, tid);
        CP_COMMIT();
    }

    const uint32_t lrow = lane & 15;
    const uint32_t lkb = (lane >> 4) << 4;     // 0 or 16 bytes

    for (int c = 0; c < NCHUNK; c++) {
        CP_WAIT_1();
        __syncthreads();   // stage c ready; all warps done computing stage c-1
        const int s = c % NSTAGE;

        // prefetch chunk c+NSTAGE-1 into the buffer freed by chunk c-1
        if (c + NSTAGE - 1 < NCHUNK) {
            const int pf = c + NSTAGE - 1;
            load_stage(a_s[pf % NSTAGE], b_s[pf % NSTAGE], rowBase, colBase,
                       pf * 64, tid);
        }
        CP_COMMIT();

        const uint32_t a_cur = a_s[s], b_cur = b_s[s];
        #pragma unroll
        for (int ks = 0; ks < 4; ks++) {
            const uint32_t kb = ks * 32 + lkb;
            uint32_t af[4][4];
            #pragma unroll
            for (int mt = 0; mt < 4; mt++) {
                uint32_t row = warp_m + mt * 16 + lrow;
                ldsm_x4(af[mt][0], af[mt][1], af[mt][2], af[mt][3],
                        a_cur + SWZ128(row * 128 + kb));
            }
            uint32_t bf[4][2];
            #pragma unroll
            for (int nt2 = 0; nt2 < 2; nt2++) {
                uint32_t row = warp_n + nt2 * 16 + lrow;
                uint32_t m0, m1, m2, m3;
                ldsm_x4(m0, m1, m2, m3, b_cur + SWZ128(row * 128 + kb));
                bf[nt2 * 2 + 0][0] = m0; bf[nt2 * 2 + 0][1] = m2;
                bf[nt2 * 2 + 1][0] = m1; bf[nt2 * 2 + 1][1] = m3;
            }
            #pragma unroll
            for (int mt = 0; mt < 4; mt++)
                #pragma unroll
                for (int nt = 0; nt < 4; nt++)
                    mma_16816(acc[mt][nt], af[mt], bf[nt]);
        }
    }
    CP_WAIT_0();

    // epilogue: sq = max(x2 + c2 - 2*dot, 0)
    const int tgrp = lane >> 2;           // 0..7 (row within 8)
    const int tpair = (lane & 3) * 2;     // 0,2,4,6 (col pair)
    #pragma unroll
    for (int mt = 0; mt < 4; mt++) {
        const int m0 = rowBase + warp_m + mt * 16 + tgrp;
        const float x2a = __ldg(&g_x2[m0]);
        const float x2b = __ldg(&g_x2[m0 + 8]);
        #pragma unroll
        for (int nt = 0; nt < 4; nt++) {
            const int n = colBase + warp_n + nt * 8 + tpair;
            const float c2a = __ldg(&g_c2[n]);
            const float c2b = __ldg(&g_c2[n + 1]);
            float2 v0, v1;
            v0.x = fmaxf(x2a + c2a - 2.0f * acc[mt][nt][0], 0.0f);
            v0.y = fmaxf(x2a + c2b - 2.0f * acc[mt][nt][1], 0.0f);
            v1.x = fmaxf(x2b + c2a - 2.0f * acc[mt][nt][2], 0.0f);
            v1.y = fmaxf(x2b + c2b - 2.0f * acc[mt][nt][3], 0.0f);
            *reinterpret_cast<float2*>(out + (size_t)m0 * K_DIM + n) = v0;
            *reinterpret_cast<float2*>(out + (size_t)(m0 + 8) * K_DIM + n) = v1;
        }
    }
}

// ---------------------------------------------------------------------------
// Kernel 3: per-row softmax over K=1024, in place + per-row loss partial.
// No max-subtraction needed: logits = -dist with dist in [0, ~45]; exp(-d)
// stays inside fp32 range and softmax is shift-invariant.
// ---------------------------------------------------------------------------
__global__ __launch_bounds__(256) void softmax_kernel(float* __restrict__ buf) {
    __shared__ float2 sbuf[8];
    const long row = blockIdx.x;
    const int tid = threadIdx.x;
    float4* rowp = reinterpret_cast<float4*>(buf + row * K_DIM);

    float4 sq = rowp[tid];
    float e0 = expf(-sqrtf(sq.x));
    float e1 = expf(-sqrtf(sq.y));
    float e2 = expf(-sqrtf(sq.z));
    float e3 = expf(-sqrtf(sq.w));

    float2 v;
    v.x = e0 + e1 + e2 + e3;                                // sum e
    v.y = e0 * sq.x + e1 * sq.y + e2 * sq.z + e3 * sq.w;    // sum e*sq

    #pragma unroll
    for (int off = 16; off > 0; off >>= 1) {
        v.x += __shfl_xor_sync(0xFFFFFFFFu, v.x, off);
        v.y += __shfl_xor_sync(0xFFFFFFFFu, v.y, off);
    }
    if ((tid & 31) == 0) sbuf[tid >> 5] = v;
    __syncthreads();
    if (tid < 32) {
        float2 w = (tid < 8) ? sbuf[tid] : make_float2(0.0f, 0.0f);
        #pragma unroll
        for (int off = 4; off > 0; off >>= 1) {
            w.x += __shfl_xor_sync(0xFFFFFFFFu, w.x, off);
            w.y += __shfl_xor_sync(0xFFFFFFFFu, w.y, off);
        }
        if (tid == 0) sbuf[0] = w;
    }
    __syncthreads();
    const float inv = 1.0f / sbuf[0].x;
    const float part = sbuf[0].y;

    float4 soft;
    soft.x = e0 * inv; soft.y = e1 * inv; soft.z = e2 * inv; soft.w = e3 * inv;
    rowp[tid] = soft;

    if (tid == 0) g_row_partial[row] = part * inv;
}

// ---------------------------------------------------------------------------
// Kernel 4: deterministic reduction of row partials -> loss at out[last].
// ---------------------------------------------------------------------------
__global__ __launch_bounds__(1024) void loss_kernel(float* __restrict__ out,
                                                    long loss_idx) {
    __shared__ float s[1024];
    const int tid = threadIdx.x;
    float acc = 0.0f;
    for (int i = tid; i < R_TOTAL; i += 1024) acc += g_row_partial[i];
    s[tid] = acc;
    __syncthreads();
    #pragma unroll
    for (int stride = 512; stride > 0; stride >>= 1) {
        if (tid < stride) s[tid] += s[tid + stride];
        __syncthreads();
    }
    if (tid == 0) out[loss_idx] = s[0] / (float)B_DIM;
}

// ---------------------------------------------------------------------------
extern "C" void kernel_launch(void* const* d_in, const int* in_sizes, int n_in,
                              void* d_out, int out_size) {
    const float* X = (const float*)d_in[0];   // (16, 8192, 256) fp32
    const float* C = (const float*)d_in[1];   // (1024, 256) fp32
    float* out = (float*)d_out;               // soft (B,N,K) then loss scalar
    (void)in_sizes; (void)n_in;

    // 1) fp16 convert + norms
    {
        int total_warps = R_TOTAL + K_DIM;
        int blocks = (total_warps + 7) / 8;
        prepack_kernel<<<blocks, 256>>>(X, C);
    }
    // 2) squared distances via HMMA GEMM (fp16, K=256) -> out used as scratch
    {
        cudaFuncSetAttribute(sqdist_hmma_kernel,
                             cudaFuncAttributeMaxDynamicSharedMemorySize,
                             SMEM_DYN);
        dim3 grid(K_DIM / BNT, R_TOTAL / BMT);   // (8, 1024)
        sqdist_hmma_kernel<<<grid, 256, SMEM_DYN>>>(out);
    }
    // 3) softmax in place + per-row loss partials
    softmax_kernel<<<R_TOTAL, 256>>>(out);
    // 4) loss scalar
    {
        long loss_idx = (long)out_size - 1;
        loss_kernel<<<1, 1024>>>(out, loss_idx);
    }
}